// round 15
// baseline (speedup 1.0000x reference)
#include <cuda_runtime.h>
#include <math.h>

#define Ss 200
#define NCTA 128
#define NPROD 16
#define GRID (NCTA + NPROD)
typedef unsigned long long u64;

__device__ float d_G0[6400 * 2048];
__device__ float d_h1buf[2][32 * 512];
__device__ float d_h2buf[2][32 * 512];
__device__ float d_lstm[6400 * 512];
__device__ float d_bce[6400];
__device__ unsigned d_cnt = 0;
__device__ unsigned d_gen = 0;
__device__ unsigned d_done[Ss];

__device__ __forceinline__ float sigf(float x) { return 1.f / (1.f + expf(-x)); }
__device__ __forceinline__ void fma2(u64& d, u64 a, u64 b)
{ asm("fma.rn.f32x2 %0, %1, %2, %0;" : "+l"(d) : "l"(a), "l"(b)); }
__device__ __forceinline__ float sum2(u64 v)
{ float lo, hi; asm("mov.b64 {%0,%1}, %2;" : "=f"(lo), "=f"(hi) : "l"(v)); return lo + hi; }
__device__ __forceinline__ unsigned ldcgu(const unsigned* p)
{ unsigned v; asm volatile("ld.global.cg.u32 %0,[%1];" : "=r"(v) : "l"(p)); return v; }
__device__ __forceinline__ void cpa16(unsigned dst, const void* src)
{ asm volatile("cp.async.cg.shared.global [%0], [%1], 16;" :: "r"(dst), "l"(src) : "memory"); }

__global__ void K_zero() { if (threadIdx.x < Ss) d_done[threadIdx.x] = 0; }

__device__ __forceinline__ void gridbar(unsigned& gen)
{
    gen++;
    __syncthreads();
    __threadfence();
    if (threadIdx.x == 0) {
        if (atomicAdd(&d_cnt, 1u) == NCTA - 1) {
            atomicExch(&d_cnt, 0u);
            __threadfence();
            atomicAdd(&d_gen, 1u);
        } else {
            while (ldcgu(&d_gen) != gen) __nanosleep(32);
        }
    }
    __syncthreads();
}

// ===== K_recur: 128 consumer CTAs (persistent pipelined LSTM) + 16 producer
// CTAs (G0 = inp @ W_ih0^T + biases, j-tile resident in smem, paced by d_done).
__global__ __launch_bounds__(256, 1) void K_recur(
    const int* __restrict__ xd, const float* __restrict__ rep,
    const float* __restrict__ past, const float* __restrict__ seq,
    const float* __restrict__ emb, const float* __restrict__ Wih0,
    const float* __restrict__ bih0, const float* __restrict__ bhh0,
    const float* __restrict__ C,
    const float* __restrict__ Whh0, const float* __restrict__ Wih1,
    const float* __restrict__ Whh1, const float* __restrict__ bih1,
    const float* __restrict__ bhh1, const float* __restrict__ init_h,
    const float* __restrict__ init_c)
{
    extern __shared__ float4 smf4[];
    const int t = threadIdx.x, cta = blockIdx.x;

    if (cta >= NCTA) {
        // ---------------- producer: j-tile (cta-NCTA)*128 ----------------
        float* inp_sm = (float*)smf4;          // [32][292]
        float* W_sm   = (float*)smf4 + 9344;   // [128][292], K padded 275->288
        const int j0 = (cta - NCTA) * 128;
        for (int idx = t; idx < 128 * 288; idx += 256) {
            int j = idx / 288, k = idx - j * 288;
            W_sm[j * 292 + k] = (k < 275) ? Wih0[(j0 + j) * 275 + k] : 0.f;
        }
        const int tx = t & 7, ty = t >> 3;
        float bias[4];
#pragma unroll
        for (int m = 0; m < 4; m++) {
            int jj = j0 + ty + 32 * m;
            bias[m] = bih0[jj] + bhh0[jj];
        }
        __syncthreads();
        for (int s = 0; s < Ss; s++) {
            for (int idx = t; idx < 32 * 288; idx += 256) {
                int b = idx / 288, k = idx - b * 288;
                float v = 0.f;
                if (k < 256) v = emb[xd[b * Ss + s] * 256 + k];
                else if (k < 275) {
                    int i = k - 256; float craw;
                    if (i < 7)       craw = rep[(b * (Ss + 1) + s) * 7 + i];
                    else if (i < 13) craw = seq[(b * (Ss + 1) + s) * 6 + (i - 7)];
                    else             craw = past[(b * (Ss + 1) + s) * 6 + (i - 13)];
                    v = C[(b * Ss + s) * 19 + i] * craw;
                }
                inp_sm[b * 292 + k] = v;
            }
            __syncthreads();
            u64 acc[4][4];
#pragma unroll
            for (int m = 0; m < 4; m++)
#pragma unroll
                for (int i = 0; i < 4; i++) acc[m][i] = 0ull;
#pragma unroll 4
            for (int k4 = 0; k4 < 72; k4++) {
                ulonglong2 a2[4], w2[4];
#pragma unroll
                for (int i = 0; i < 4; i++)
                    a2[i] = *(const ulonglong2*)&inp_sm[(tx + 8 * i) * 292 + k4 * 4];
#pragma unroll
                for (int m = 0; m < 4; m++)
                    w2[m] = *(const ulonglong2*)&W_sm[(ty + 32 * m) * 292 + k4 * 4];
#pragma unroll
                for (int m = 0; m < 4; m++)
#pragma unroll
                    for (int i = 0; i < 4; i++) {
                        fma2(acc[m][i], w2[m].x, a2[i].x);
                        fma2(acc[m][i], w2[m].y, a2[i].y);
                    }
            }
#pragma unroll
            for (int m = 0; m < 4; m++) {
                int jj = j0 + ty + 32 * m;
#pragma unroll
                for (int i = 0; i < 4; i++)
                    d_G0[((size_t)s * 2048 + jj) * 32 + (tx + 8 * i)] =
                        sum2(acc[m][i]) + bias[m];
            }
            __syncthreads();
            if (t == 0) { __threadfence(); atomicAdd(&d_done[s], 1u); }
        }
        return;
    }

    // ---------------- consumer: recurrence ----------------
    float4* bufA = smf4;            // h1(tau-1): [b][k4 ^ (b&7)]
    float4* bufB = smf4 + 4096;     // h2(tau-2)
    float4* W0   = smf4 + 8192;     // [o][k4 ^ (o>>2)]
    float4* W1   = smf4 + 10240;    // [half][o][k4 ^ (o>>2)]
    float* redL0 = (float*)bufA;    // aliased partials (post-sync)
    float* redL1 = (float*)bufB;

    const int CB = cta * 4;
    const int wid = t >> 5, lane = t & 31;
    const int og = lane >> 3, bg = lane & 7;
    unsigned gen = atomicAdd(&d_gen, 0u);
    const unsigned baseA = (unsigned)__cvta_generic_to_shared(bufA);
    const unsigned baseB = (unsigned)__cvta_generic_to_shared(bufB);

    const float4* Whh0f = (const float4*)Whh0;
    const float4* Wih1f = (const float4*)Wih1;
    const float4* Whh1f = (const float4*)Whh1;
    for (int idx = t; idx < 2048; idx += 256) {
        int o = idx >> 7, k4 = idx & 127, g = o >> 2, nl = o & 3;
        W0[o * 128 + (k4 ^ g)] = Whh0f[(size_t)(g * 512 + CB + nl) * 128 + k4];
    }
    for (int idx = t; idx < 4096; idx += 256) {
        int half = idx >> 11, o = (idx >> 7) & 15, k4 = idx & 127;
        int g = o >> 2, nl = o & 3;
        const float4* src = half ? Whh1f : Wih1f;
        W1[half * 2048 + o * 128 + (k4 ^ g)] =
            src[(size_t)(g * 512 + CB + nl) * 128 + k4];
    }

    float creg;
    float bs0 = 0.f, bs1 = 0.f, bs2 = 0.f, bs3 = 0.f;
    {
        int nl = (t & 127) >> 5, b = t & 31;
        if (t < 128) creg = init_c[b * 512 + CB + nl];
        else {
            creg = init_c[16384 + b * 512 + CB + nl];
            bs0 = bih1[0 * 512 + CB + nl] + bhh1[0 * 512 + CB + nl];
            bs1 = bih1[1 * 512 + CB + nl] + bhh1[1 * 512 + CB + nl];
            bs2 = bih1[2 * 512 + CB + nl] + bhh1[2 * 512 + CB + nl];
            bs3 = bih1[3 * 512 + CB + nl] + bhh1[3 * 512 + CB + nl];
        }
    }
    {
        int gid = cta * 256 + t;
        if (gid < 16384) {
            d_h1buf[1][gid] = init_h[gid];
            d_h2buf[1][gid] = init_h[16384 + gid];
        }
    }
    gridbar(gen);

    for (int tau = 0; tau <= Ss; tau++) {
        // stage h via cp.async (swizzle-preserving, no register pressure)
        const float4* srcA = (const float4*)d_h1buf[(tau + 1) & 1];
        for (int idx = t; idx < 4096; idx += 256) {
            int b = idx >> 7, k4 = idx & 127;
            cpa16(baseA + (unsigned)((((b << 7) | (k4 ^ (b & 7)))) << 4), srcA + idx);
        }
        if (tau >= 1) {
            const float4* srcB = (const float4*)d_h2buf[tau & 1];
            for (int idx = t; idx < 4096; idx += 256) {
                int b = idx >> 7, k4 = idx & 127;
                cpa16(baseB + (unsigned)((((b << 7) | (k4 ^ (b & 7)))) << 4), srcB + idx);
            }
        }
        asm volatile("cp.async.commit_group;" ::: "memory");
        if (t == 0 && tau < Ss)
            while (ldcgu(&d_done[tau]) < (unsigned)NPROD) __nanosleep(64);
        asm volatile("cp.async.wait_group 0;" ::: "memory");
        __syncthreads();

        float g0pf[4];
        if (t < 128 && tau < Ss) {
            int nl = t >> 5, b = t & 31;
            const float* g0 = d_G0 + (size_t)tau * 65536;
#pragma unroll
            for (int g = 0; g < 4; g++)
                g0pf[g] = __ldcg(&g0[(g * 512 + CB + nl) * 32 + b]);
        }

        const bool act = (wid < 4) ? (tau < Ss) : (tau >= 1);
        u64 acc[4][4];
        if (act) {
#pragma unroll
            for (int i = 0; i < 4; i++)
#pragma unroll
                for (int j = 0; j < 4; j++) acc[i][j] = 0ull;

            const float4* hbase;
            const float4* wbase;
            int k40, nk4;
            if (wid < 4) { hbase = bufA; wbase = W0; k40 = wid * 32; nk4 = 32; }
            else {
                int m = wid - 4, half = m >> 1;
                hbase = half ? bufB : bufA;
                wbase = W1 + half * 2048;
                k40 = (m & 1) * 64; nk4 = 64;
            }
            const float4* hp[4];
            const float4* wp[4];
#pragma unroll
            for (int j = 0; j < 4; j++) hp[j] = hbase + (bg + 8 * j) * 128;
#pragma unroll
            for (int i = 0; i < 4; i++) wp[i] = wbase + (og * 4 + i) * 128;

#pragma unroll 4
            for (int kk = 0; kk < nk4; kk++) {
                int k4 = k40 + kk;
                int kh = k4 ^ bg, kw = k4 ^ og;
                ulonglong2 h0 = *(const ulonglong2*)(hp[0] + kh);
                ulonglong2 h1 = *(const ulonglong2*)(hp[1] + kh);
                ulonglong2 h2 = *(const ulonglong2*)(hp[2] + kh);
                ulonglong2 h3 = *(const ulonglong2*)(hp[3] + kh);
#pragma unroll
                for (int i = 0; i < 4; i++) {
                    ulonglong2 w = *(const ulonglong2*)(wp[i] + kw);
                    fma2(acc[i][0], w.x, h0.x); fma2(acc[i][0], w.y, h0.y);
                    fma2(acc[i][1], w.x, h1.x); fma2(acc[i][1], w.y, h1.y);
                    fma2(acc[i][2], w.x, h2.x); fma2(acc[i][2], w.y, h2.y);
                    fma2(acc[i][3], w.x, h3.x); fma2(acc[i][3], w.y, h3.y);
                }
            }
        }
        __syncthreads();   // k-loop reads done before red aliasing
        if (act) {
            float* red = (wid < 4) ? redL0 : redL1;
            int w4 = wid & 3;
#pragma unroll
            for (int i = 0; i < 4; i++) {
                int o = og * 4 + i;
#pragma unroll
                for (int j = 0; j < 4; j++) {
                    int b = bg + 8 * j;
                    red[w4 * 512 + o * 32 + (b ^ (og << 3))] = sum2(acc[i][j]);
                }
            }
        }
        __syncthreads();

        if (t < 128) {
            if (tau < Ss) {
                int nl = t >> 5, b = t & 31;
                float gate[4];
#pragma unroll
                for (int g = 0; g < 4; g++) {
                    int ix = (g * 4 + nl) * 32 + (b ^ (g << 3));
                    gate[g] = redL0[ix] + redL0[512 + ix] + redL0[1024 + ix]
                            + redL0[1536 + ix] + g0pf[g];
                }
                float c = sigf(gate[1]) * creg + sigf(gate[0]) * tanhf(gate[2]);
                creg = c;
                d_h1buf[tau & 1][b * 512 + CB + nl] = sigf(gate[3]) * tanhf(c);
            }
        } else {
            if (tau >= 1) {
                int nl = (t & 127) >> 5, b = t & 31;
                float gate[4];
#pragma unroll
                for (int g = 0; g < 4; g++) {
                    int ix = (g * 4 + nl) * 32 + (b ^ (g << 3));
                    gate[g] = redL1[ix] + redL1[512 + ix] + redL1[1024 + ix]
                            + redL1[1536 + ix];
                }
                float c = sigf(gate[1] + bs1) * creg
                        + sigf(gate[0] + bs0) * tanhf(gate[2] + bs2);
                creg = c;
                float h = sigf(gate[3] + bs3) * tanhf(c);
                d_h2buf[(tau + 1) & 1][b * 512 + CB + nl] = h;
                d_lstm[((size_t)b * Ss + (tau - 1)) * 512 + CB + nl] = h;
            }
        }
        gridbar(gen);
    }
}

// ===== K_pred: gathered head dot + BCE =====
__global__ __launch_bounds__(256) void K_pred(
    const int* __restrict__ qt, const float* __restrict__ target,
    const float* __restrict__ rep, const float* __restrict__ past,
    const float* __restrict__ seq, const float* __restrict__ Wp,
    const float* __restrict__ bp, const float* __restrict__ C,
    float* __restrict__ out)
{
    int r = (blockIdx.x * 256 + threadIdx.x) >> 5;
    int lane = threadIdx.x & 31;
    if (r >= 6400) return;
    int b = r / Ss, s = r % Ss, q = qt[r];
    const float* wrow = Wp + (size_t)q * 531;
    float acc = 0.f;
#pragma unroll
    for (int it = 0; it < 17; it++) {
        int idx = lane + 32 * it;
        if (idx < 531) {
            float v;
            if (idx < 512) v = d_lstm[(size_t)r * 512 + idx];
            else {
                int i = idx - 512; float craw;
                if (i < 7)       craw = rep[(b * (Ss + 1) + s + 1) * 7 + i];
                else if (i < 13) craw = seq[(b * (Ss + 1) + s + 1) * 6 + (i - 7)];
                else             craw = past[(b * (Ss + 1) + s + 1) * 6 + (i - 13)];
                v = C[(b * Ss + s) * 19 + i] * craw;
            }
            acc = fmaf(wrow[idx], v, acc);
        }
    }
#pragma unroll
    for (int o = 16; o > 0; o >>= 1) acc += __shfl_xor_sync(0xffffffffu, acc, o);
    if (lane == 0) {
        float p = 0.f, tm = 0.f, bce = 0.f;
        if (q > 0) {
            float x = acc + bp[q];
            p = 1.f / (1.f + expf(-x));
            float tt = target[r];
            bce = fmaxf(x, 0.f) - x * tt + log1pf(expf(-fabsf(x)));
            tm = tt;
        }
        out[1 + r] = p;
        out[1 + 6400 + r] = tm;
        d_bce[r] = bce;
    }
}

__global__ void K_loss(const int* __restrict__ qt, float* __restrict__ out)
{
    __shared__ float s1[256], s2[256];
    int t = threadIdx.x;
    float a = 0.f, c = 0.f;
    for (int r = t; r < 6400; r += 256) {
        a += d_bce[r];
        c += (qt[r] > 0) ? 1.f : 0.f;
    }
    s1[t] = a; s2[t] = c;
    __syncthreads();
    for (int o = 128; o > 0; o >>= 1) {
        if (t < o) { s1[t] += s1[t + o]; s2[t] += s2[t + o]; }
        __syncthreads();
    }
    if (t == 0) out[0] = s1[0] / s2[0];
}

extern "C" void kernel_launch(void* const* d_in, const int* in_sizes, int n_in,
                              void* d_out, int out_size)
{
    const int*   xd   = (const int*)  d_in[0];
    const int*   qt   = (const int*)  d_in[1];
    const float* tgt  = (const float*)d_in[2];
    const float* rep  = (const float*)d_in[3];
    const float* past = (const float*)d_in[4];
    const float* seq  = (const float*)d_in[5];
    const float* emb  = (const float*)d_in[6];
    const float* Wih0 = (const float*)d_in[7];
    const float* Whh0 = (const float*)d_in[8];
    const float* bih0 = (const float*)d_in[9];
    const float* bhh0 = (const float*)d_in[10];
    const float* Wih1 = (const float*)d_in[11];
    const float* Whh1 = (const float*)d_in[12];
    const float* bih1 = (const float*)d_in[13];
    const float* bhh1 = (const float*)d_in[14];
    const float* Wp   = (const float*)d_in[15];
    const float* bp   = (const float*)d_in[16];
    const float* C    = (const float*)d_in[17];
    const float* ih   = (const float*)d_in[18];
    const float* ic   = (const float*)d_in[19];
    float* out = (float*)d_out;

    const int smem_rc = 14336 * 16;  // 229,376 B
    cudaFuncSetAttribute(K_recur, cudaFuncAttributeMaxDynamicSharedMemorySize, smem_rc);

    K_zero<<<1, 256>>>();
    K_recur<<<GRID, 256, smem_rc>>>(xd, rep, past, seq, emb, Wih0, bih0, bhh0, C,
                                    Whh0, Wih1, Whh1, bih1, bhh1, ih, ic);
    K_pred<<<800, 256>>>(qt, tgt, rep, past, seq, Wp, bp, C, out);
    K_loss<<<1, 256>>>(qt, out);
}

// round 16
// speedup vs baseline: 1.2570x; 1.2570x over previous
#include <cuda_runtime.h>
#include <math.h>

#define Ss 200
#define NCTA 128
typedef unsigned long long u64;

__device__ float d_G0[6400 * 2048];
__device__ float d_h1buf[2][32 * 512];
__device__ float d_h2buf[2][32 * 512];
__device__ float d_lstm[6400 * 512];
__device__ float d_bce[6400];
__device__ unsigned d_flags[NCTA];

__device__ __forceinline__ float sigf(float x) { return 1.f / (1.f + expf(-x)); }
__device__ __forceinline__ void fma2(u64& d, u64 a, u64 b)
{ asm("fma.rn.f32x2 %0, %1, %2, %0;" : "+l"(d) : "l"(a), "l"(b)); }
__device__ __forceinline__ float sum2(u64 v)
{ float lo, hi; asm("mov.b64 {%0,%1}, %2;" : "=f"(lo), "=f"(hi) : "l"(v)); return lo + hi; }

// ===== K_ingate: G0[s][g*512+n][b] = inp @ W_ih0^T + bih0 + bhh0 =====
// grid (16 j-tiles, 25 s-groups); each CTA keeps its W-tile in smem for 8 s.
__global__ __launch_bounds__(256) void K_ingate(
    const int* __restrict__ xd, const float* __restrict__ rep,
    const float* __restrict__ past, const float* __restrict__ seq,
    const float* __restrict__ emb, const float* __restrict__ Wih0,
    const float* __restrict__ bih0, const float* __restrict__ bhh0,
    const float* __restrict__ C)
{
    extern __shared__ float sh[];
    float* inp_sm = sh;            // [32][292] (K 275 padded to 288)
    float* W_sm   = sh + 32 * 292; // [128][36] -> use stride 36 per 32k? no: [128][292] too big
    // W layout: [128][36] per k-tile is R13's scheme; here keep full K rows: [128][292]
    // smem budget: 32*292 + 128*292 floats = 46720 f = 186,880 B
    const int t = threadIdx.x, j0 = blockIdx.x * 128, s0 = blockIdx.y * 8;
    const int tx = t & 7, ty = t >> 3;

    for (int idx = t; idx < 128 * 288; idx += 256) {
        int j = idx / 288, k = idx - j * 288;
        W_sm[j * 292 + k] = (k < 275) ? Wih0[(j0 + j) * 275 + k] : 0.f;
    }
    float bias[4];
#pragma unroll
    for (int m = 0; m < 4; m++) bias[m] = bih0[j0 + ty + 32 * m] + bhh0[j0 + ty + 32 * m];

    for (int si = 0; si < 8; si++) {
        int s = s0 + si;
        __syncthreads();
        for (int idx = t; idx < 32 * 288; idx += 256) {
            int b = idx / 288, k = idx - b * 288;
            float v = 0.f;
            if (k < 256) v = emb[xd[b * Ss + s] * 256 + k];
            else if (k < 275) {
                int i = k - 256; float craw;
                if (i < 7)       craw = rep[(b * (Ss + 1) + s) * 7 + i];
                else if (i < 13) craw = seq[(b * (Ss + 1) + s) * 6 + (i - 7)];
                else             craw = past[(b * (Ss + 1) + s) * 6 + (i - 13)];
                v = C[(b * Ss + s) * 19 + i] * craw;
            }
            inp_sm[b * 292 + k] = v;
        }
        __syncthreads();
        u64 acc[4][4];
#pragma unroll
        for (int m = 0; m < 4; m++)
#pragma unroll
            for (int i = 0; i < 4; i++) acc[m][i] = 0ull;
#pragma unroll 4
        for (int k4 = 0; k4 < 72; k4++) {
            ulonglong2 a2[4], w2[4];
#pragma unroll
            for (int i = 0; i < 4; i++)
                a2[i] = *(const ulonglong2*)&inp_sm[(tx + 8 * i) * 292 + k4 * 4];
#pragma unroll
            for (int m = 0; m < 4; m++)
                w2[m] = *(const ulonglong2*)&W_sm[(ty + 32 * m) * 292 + k4 * 4];
#pragma unroll
            for (int m = 0; m < 4; m++)
#pragma unroll
                for (int i = 0; i < 4; i++) {
                    fma2(acc[m][i], w2[m].x, a2[i].x);
                    fma2(acc[m][i], w2[m].y, a2[i].y);
                }
        }
#pragma unroll
        for (int m = 0; m < 4; m++) {
            int jj = j0 + ty + 32 * m;
#pragma unroll
            for (int i = 0; i < 4; i++)
                d_G0[((size_t)s * 2048 + jj) * 32 + (tx + 8 * i)] =
                    sum2(acc[m][i]) + bias[m];
        }
    }
}

// ===== flag-array grid barrier: no hot atomic line =====
__device__ __forceinline__ void flagbar(unsigned gen, int cta, int t)
{
    __syncthreads();
    __threadfence();
    if (t == 0)
        asm volatile("st.global.cg.u32 [%0], %1;" :: "l"(d_flags + cta), "r"(gen) : "memory");
    if (t < NCTA) {
        unsigned v;
        do {
            asm volatile("ld.global.cg.u32 %0,[%1];" : "=r"(v) : "l"(d_flags + t) : "memory");
            if (v < gen) __nanosleep(32);
        } while (v < gen);
    }
    __syncthreads();
    __threadfence();
}

// ===== K_recur: persistent pipelined 2-layer LSTM (R13 engine + flagbar) =====
__global__ __launch_bounds__(256, 1) void K_recur(
    const float* __restrict__ Whh0, const float* __restrict__ Wih1,
    const float* __restrict__ Whh1, const float* __restrict__ bih1,
    const float* __restrict__ bhh1, const float* __restrict__ init_h,
    const float* __restrict__ init_c)
{
    extern __shared__ float4 smf4[];
    float4* bufA = smf4;            // h1(tau-1): [b][k4 ^ (b&7)]
    float4* bufB = smf4 + 4096;     // h2(tau-2)
    float4* W0   = smf4 + 8192;     // [o][k4 ^ (o>>2)]
    float4* W1   = smf4 + 10240;    // [half][o][k4 ^ (o>>2)]
    float* redL0 = (float*)bufA;    // aliased partials (post-sync)
    float* redL1 = (float*)bufB;

    const int t = threadIdx.x, cta = blockIdx.x, CB = cta * 4;
    const int wid = t >> 5, lane = t & 31;
    const int og = lane >> 3, bg = lane & 7;
    unsigned gen;
    asm volatile("ld.global.cg.u32 %0,[%1];" : "=r"(gen) : "l"(d_flags + cta));

    const float4* Whh0f = (const float4*)Whh0;
    const float4* Wih1f = (const float4*)Wih1;
    const float4* Whh1f = (const float4*)Whh1;
    for (int idx = t; idx < 2048; idx += 256) {
        int o = idx >> 7, k4 = idx & 127, g = o >> 2, nl = o & 3;
        W0[o * 128 + (k4 ^ g)] = Whh0f[(size_t)(g * 512 + CB + nl) * 128 + k4];
    }
    for (int idx = t; idx < 4096; idx += 256) {
        int half = idx >> 11, o = (idx >> 7) & 15, k4 = idx & 127;
        int g = o >> 2, nl = o & 3;
        const float4* src = half ? Whh1f : Wih1f;
        W1[half * 2048 + o * 128 + (k4 ^ g)] =
            src[(size_t)(g * 512 + CB + nl) * 128 + k4];
    }

    float creg;
    float bs0 = 0.f, bs1 = 0.f, bs2 = 0.f, bs3 = 0.f;
    {
        int nl = (t & 127) >> 5, b = t & 31;
        if (t < 128) creg = init_c[b * 512 + CB + nl];
        else {
            creg = init_c[16384 + b * 512 + CB + nl];
            bs0 = bih1[0 * 512 + CB + nl] + bhh1[0 * 512 + CB + nl];
            bs1 = bih1[1 * 512 + CB + nl] + bhh1[1 * 512 + CB + nl];
            bs2 = bih1[2 * 512 + CB + nl] + bhh1[2 * 512 + CB + nl];
            bs3 = bih1[3 * 512 + CB + nl] + bhh1[3 * 512 + CB + nl];
        }
    }
    {
        int gid = cta * 256 + t;
        if (gid < 16384) {
            d_h1buf[1][gid] = init_h[gid];
            d_h2buf[1][gid] = init_h[16384 + gid];
        }
    }
    gen++;
    flagbar(gen, cta, t);

    for (int tau = 0; tau <= Ss; tau++) {
        // prefetch G0 for L0 epilogue (hidden behind staging + GEMM)
        float g0pf[4];
        if (t < 128 && tau < Ss) {
            int nl = t >> 5, b = t & 31;
            const float* g0 = d_G0 + (size_t)tau * 65536;
#pragma unroll
            for (int g = 0; g < 4; g++)
                g0pf[g] = __ldcg(&g0[(g * 512 + CB + nl) * 32 + b]);
        }
        // stage h (swizzled)
        const float4* srcA = (const float4*)d_h1buf[(tau + 1) & 1];
        for (int idx = t; idx < 4096; idx += 256) {
            int b = idx >> 7, k4 = idx & 127;
            bufA[b * 128 + (k4 ^ (b & 7))] = __ldcg(srcA + idx);
        }
        if (tau >= 1) {
            const float4* srcB = (const float4*)d_h2buf[tau & 1];
            for (int idx = t; idx < 4096; idx += 256) {
                int b = idx >> 7, k4 = idx & 127;
                bufB[b * 128 + (k4 ^ (b & 7))] = __ldcg(srcB + idx);
            }
        }
        __syncthreads();

        const bool act = (wid < 4) ? (tau < Ss) : (tau >= 1);
        u64 acc[4][4];
        if (act) {
#pragma unroll
            for (int i = 0; i < 4; i++)
#pragma unroll
                for (int j = 0; j < 4; j++) acc[i][j] = 0ull;

            const float4* hbase;
            const float4* wbase;
            int k40, nk4;
            if (wid < 4) { hbase = bufA; wbase = W0; k40 = wid * 32; nk4 = 32; }
            else {
                int m = wid - 4, half = m >> 1;
                hbase = half ? bufB : bufA;
                wbase = W1 + half * 2048;
                k40 = (m & 1) * 64; nk4 = 64;
            }
            const float4* hp[4];
            const float4* wp[4];
#pragma unroll
            for (int j = 0; j < 4; j++) hp[j] = hbase + (bg + 8 * j) * 128;
#pragma unroll
            for (int i = 0; i < 4; i++) wp[i] = wbase + (og * 4 + i) * 128;

#pragma unroll 4
            for (int kk = 0; kk < nk4; kk++) {
                int k4 = k40 + kk;
                int kh = k4 ^ bg, kw = k4 ^ og;
                ulonglong2 h0 = *(const ulonglong2*)(hp[0] + kh);
                ulonglong2 h1 = *(const ulonglong2*)(hp[1] + kh);
                ulonglong2 h2 = *(const ulonglong2*)(hp[2] + kh);
                ulonglong2 h3 = *(const ulonglong2*)(hp[3] + kh);
#pragma unroll
                for (int i = 0; i < 4; i++) {
                    ulonglong2 w = *(const ulonglong2*)(wp[i] + kw);
                    fma2(acc[i][0], w.x, h0.x); fma2(acc[i][0], w.y, h0.y);
                    fma2(acc[i][1], w.x, h1.x); fma2(acc[i][1], w.y, h1.y);
                    fma2(acc[i][2], w.x, h2.x); fma2(acc[i][2], w.y, h2.y);
                    fma2(acc[i][3], w.x, h3.x); fma2(acc[i][3], w.y, h3.y);
                }
            }
        }
        __syncthreads();   // k-loop reads done before red aliasing
        if (act) {
            float* red = (wid < 4) ? redL0 : redL1;
            int w4 = wid & 3;
#pragma unroll
            for (int i = 0; i < 4; i++) {
                int o = og * 4 + i;
#pragma unroll
                for (int j = 0; j < 4; j++) {
                    int b = bg + 8 * j;
                    red[w4 * 512 + o * 32 + (b ^ (og << 3))] = sum2(acc[i][j]);
                }
            }
        }
        __syncthreads();

        if (t < 128) {
            if (tau < Ss) {
                int nl = t >> 5, b = t & 31;
                float gate[4];
#pragma unroll
                for (int g = 0; g < 4; g++) {
                    int ix = (g * 4 + nl) * 32 + (b ^ (g << 3));
                    gate[g] = redL0[ix] + redL0[512 + ix] + redL0[1024 + ix]
                            + redL0[1536 + ix] + g0pf[g];
                }
                float c = sigf(gate[1]) * creg + sigf(gate[0]) * tanhf(gate[2]);
                creg = c;
                d_h1buf[tau & 1][b * 512 + CB + nl] = sigf(gate[3]) * tanhf(c);
            }
        } else {
            if (tau >= 1) {
                int nl = (t & 127) >> 5, b = t & 31;
                float gate[4];
#pragma unroll
                for (int g = 0; g < 4; g++) {
                    int ix = (g * 4 + nl) * 32 + (b ^ (g << 3));
                    gate[g] = redL1[ix] + redL1[512 + ix] + redL1[1024 + ix]
                            + redL1[1536 + ix];
                }
                float c = sigf(gate[1] + bs1) * creg
                        + sigf(gate[0] + bs0) * tanhf(gate[2] + bs2);
                creg = c;
                float h = sigf(gate[3] + bs3) * tanhf(c);
                d_h2buf[(tau + 1) & 1][b * 512 + CB + nl] = h;
                d_lstm[((size_t)b * Ss + (tau - 1)) * 512 + CB + nl] = h;
            }
        }
        gen++;
        flagbar(gen, cta, t);
    }
}

// ===== K_pred: gathered head dot + BCE =====
__global__ __launch_bounds__(256) void K_pred(
    const int* __restrict__ qt, const float* __restrict__ target,
    const float* __restrict__ rep, const float* __restrict__ past,
    const float* __restrict__ seq, const float* __restrict__ Wp,
    const float* __restrict__ bp, const float* __restrict__ C,
    float* __restrict__ out)
{
    int r = (blockIdx.x * 256 + threadIdx.x) >> 5;
    int lane = threadIdx.x & 31;
    if (r >= 6400) return;
    int b = r / Ss, s = r % Ss, q = qt[r];
    const float* wrow = Wp + (size_t)q * 531;
    float acc = 0.f;
#pragma unroll
    for (int it = 0; it < 17; it++) {
        int idx = lane + 32 * it;
        if (idx < 531) {
            float v;
            if (idx < 512) v = d_lstm[(size_t)r * 512 + idx];
            else {
                int i = idx - 512; float craw;
                if (i < 7)       craw = rep[(b * (Ss + 1) + s + 1) * 7 + i];
                else if (i < 13) craw = seq[(b * (Ss + 1) + s + 1) * 6 + (i - 7)];
                else             craw = past[(b * (Ss + 1) + s + 1) * 6 + (i - 13)];
                v = C[(b * Ss + s) * 19 + i] * craw;
            }
            acc = fmaf(wrow[idx], v, acc);
        }
    }
#pragma unroll
    for (int o = 16; o > 0; o >>= 1) acc += __shfl_xor_sync(0xffffffffu, acc, o);
    if (lane == 0) {
        float p = 0.f, tm = 0.f, bce = 0.f;
        if (q > 0) {
            float x = acc + bp[q];
            p = 1.f / (1.f + expf(-x));
            float tt = target[r];
            bce = fmaxf(x, 0.f) - x * tt + log1pf(expf(-fabsf(x)));
            tm = tt;
        }
        out[1 + r] = p;
        out[1 + 6400 + r] = tm;
        d_bce[r] = bce;
    }
}

__global__ void K_loss(const int* __restrict__ qt, float* __restrict__ out)
{
    __shared__ float s1[256], s2[256];
    int t = threadIdx.x;
    float a = 0.f, c = 0.f;
    for (int r = t; r < 6400; r += 256) {
        a += d_bce[r];
        c += (qt[r] > 0) ? 1.f : 0.f;
    }
    s1[t] = a; s2[t] = c;
    __syncthreads();
    for (int o = 128; o > 0; o >>= 1) {
        if (t < o) { s1[t] += s1[t + o]; s2[t] += s2[t + o]; }
        __syncthreads();
    }
    if (t == 0) out[0] = s1[0] / s2[0];
}

extern "C" void kernel_launch(void* const* d_in, const int* in_sizes, int n_in,
                              void* d_out, int out_size)
{
    const int*   xd   = (const int*)  d_in[0];
    const int*   qt   = (const int*)  d_in[1];
    const float* tgt  = (const float*)d_in[2];
    const float* rep  = (const float*)d_in[3];
    const float* past = (const float*)d_in[4];
    const float* seq  = (const float*)d_in[5];
    const float* emb  = (const float*)d_in[6];
    const float* Wih0 = (const float*)d_in[7];
    const float* Whh0 = (const float*)d_in[8];
    const float* bih0 = (const float*)d_in[9];
    const float* bhh0 = (const float*)d_in[10];
    const float* Wih1 = (const float*)d_in[11];
    const float* Whh1 = (const float*)d_in[12];
    const float* bih1 = (const float*)d_in[13];
    const float* bhh1 = (const float*)d_in[14];
    const float* Wp   = (const float*)d_in[15];
    const float* bp   = (const float*)d_in[16];
    const float* C    = (const float*)d_in[17];
    const float* ih   = (const float*)d_in[18];
    const float* ic   = (const float*)d_in[19];
    float* out = (float*)d_out;

    const int smem_ig = (32 * 292 + 128 * 292) * 4;  // 186,880 B
    const int smem_rc = 14336 * 16;                  // 229,376 B
    cudaFuncSetAttribute(K_ingate, cudaFuncAttributeMaxDynamicSharedMemorySize, smem_ig);
    cudaFuncSetAttribute(K_recur,  cudaFuncAttributeMaxDynamicSharedMemorySize, smem_rc);

    dim3 gg(16, 25);
    K_ingate<<<gg, 256, smem_ig>>>(xd, rep, past, seq, emb, Wih0, bih0, bhh0, C);
    K_recur<<<NCTA, 256, smem_rc>>>(Whh0, Wih1, Whh1, bih1, bhh1, ih, ic);
    K_pred<<<800, 256>>>(qt, tgt, rep, past, seq, Wp, bp, C, out);
    K_loss<<<1, 256>>>(qt, out);
}